// round 13
// baseline (speedup 1.0000x reference)
#include <cuda_runtime.h>
#include <stdint.h>

// ---------------------------------------------------------------------------
// KMaxPool: per row of 4096 fp32, top-8 values in original index order.
// One warp per row, single pass. R12 skeleton (regs 32, 128-thr blocks).
//   - warp top-8 DISTRIBUTED in lanes 0..7 (val desc), vmin = lane7 val
//   - HIERARCHICAL gates: 1 ballot per 8-elem pair (depends on 2 loads only)
//     -> quad ballots -> element ballots. Steady serial gates/iter: 4 -> 2.
//   - lean insert: no re-ballot prune (stale insert is a provable no-op),
//     vmin refreshed once per qualifying element after the pop loop
//   - __ldcs streaming loads (read-once data)
//   - epilogue: rank lanes 0..7 by original index, scatter-store 8 floats
// ---------------------------------------------------------------------------

#define FULLMASK 0xffffffffu

// Exact per-element processing: pop qualifying lanes in ascending-lane
// (= ascending-index) order and do the distributed shfl insert. A candidate
// made stale by a previous insert (bv <= val[7]) yields keep=true on every
// lane -> list unchanged; correctness preserved without re-ballot pruning.
static __device__ __forceinline__ void proc(float v, uint32_t ubase,
                                            float& val, uint32_t& idx,
                                            float& vmin, bool lane0) {
    unsigned m = __ballot_sync(FULLMASK, v > vmin);
    if (!m) return;
    do {
        const int L = __ffs(m) - 1;
        m &= m - 1;
        const float    bv = __shfl_sync(FULLMASK, v, L);
        const uint32_t bi = ubase + ((uint32_t)L << 2);

        const float    pv = __shfl_up_sync(FULLMASK, val, 1);
        const uint32_t pi = __shfl_up_sync(FULLMASK, idx, 1);
        const bool keep = (val >= bv);            // incumbent wins ties
        const bool pk   = lane0 || (pv >= bv);    // lane0: conceptual prev=+inf
        val = keep ? val : (pk ? bv : pv);
        idx = keep ? idx : (pk ? bi : pi);
    } while (m);
    vmin = __shfl_sync(FULLMASK, val, 7);
}

static __device__ __forceinline__ float max4(uint4 q) {
    return fmaxf(fmaxf(__uint_as_float(q.x), __uint_as_float(q.y)),
                 fmaxf(__uint_as_float(q.z), __uint_as_float(q.w)));
}

// Element scan of one quad (no gate; caller already gated).
static __device__ __forceinline__ void scan4(uint4 q, uint32_t ubase,
                                             float& val, uint32_t& idx,
                                             float& vmin, bool lane0) {
    proc(__uint_as_float(q.x), ubase + 0, val, idx, vmin, lane0);
    proc(__uint_as_float(q.y), ubase + 1, val, idx, vmin, lane0);
    proc(__uint_as_float(q.z), ubase + 2, val, idx, vmin, lane0);
    proc(__uint_as_float(q.w), ubase + 3, val, idx, vmin, lane0);
}

// Pair gate: one ballot per 8 elements; quad ballots inside on a hit.
static __device__ __forceinline__ void pair(uint4 a, uint4 b,
                                            uint32_t ua, uint32_t ub,
                                            float& val, uint32_t& idx,
                                            float& vmin, bool lane0) {
    const float ma = max4(a);
    const float mb = max4(b);
    if (__ballot_sync(FULLMASK, fmaxf(ma, mb) > vmin)) {
        if (__ballot_sync(FULLMASK, ma > vmin)) scan4(a, ua, val, idx, vmin, lane0);
        if (__ballot_sync(FULLMASK, mb > vmin)) scan4(b, ub, val, idx, vmin, lane0);
    }
}

__global__ void __launch_bounds__(128) kmax8_kernel(const float* __restrict__ x,
                                                    float* __restrict__ out,
                                                    int nrows) {
    const int gw   = (int)((blockIdx.x * blockDim.x + threadIdx.x) >> 5);
    const int lane = threadIdx.x & 31;
    if (gw >= nrows) return;

    const uint4* row = reinterpret_cast<const uint4*>(x) + (size_t)gw * 1024;

    float    val  = __int_as_float(0xff800000);  // -inf (lanes 0..7 = top-8)
    uint32_t idx  = 0;
    float    vmin = __int_as_float(0xff800000);
    const bool lane0 = (lane == 0);

    // 8 batches x (4 float4 streaming loads = 16 elements) per lane.
#pragma unroll 1
    for (int it = 0; it < 8; ++it) {
        const uint4* p = row + it * 128 + lane;
        uint4 a = __ldcs(p);
        uint4 b = __ldcs(p + 32);
        uint4 c = __ldcs(p + 64);
        uint4 d = __ldcs(p + 96);

        const uint32_t u0 = (uint32_t)(it * 512);
        // pair(a,b) gate depends only on a,b: c,d remain in flight meanwhile
        pair(a, b, u0 + 0,   u0 + 128, val, idx, vmin, lane0);
        pair(c, d, u0 + 256, u0 + 384, val, idx, vmin, lane0);
    }

    // Epilogue: lanes 0..7 hold the top-8 (val desc, unique idx).
    // rank = number of held indices smaller than mine -> output position.
    int rank = 0;
#pragma unroll
    for (int dd = 1; dd < 8; ++dd) {
        uint32_t oi = __shfl_sync(FULLMASK, idx, (lane + dd) & 7);
        rank += (oi < idx) ? 1 : 0;
    }
    if (lane < 8) out[(size_t)gw * 8 + rank] = val;
}

extern "C" void kernel_launch(void* const* d_in, const int* in_sizes, int n_in,
                              void* d_out, int out_size) {
    const float* x = (const float*)d_in[0];
    float* out = (float*)d_out;
    int nrows = in_sizes[0] / 4096;
    const int threads = 128;                      // 4 warps/block
    const int warps_per_block = threads / 32;
    int blocks = (nrows + warps_per_block - 1) / warps_per_block;
    kmax8_kernel<<<blocks, threads>>>(x, out, nrows);
}